// round 6
// baseline (speedup 1.0000x reference)
#include <cuda_runtime.h>
#include <math.h>
#include <stdint.h>

#define NB 8
#define NT 2048
#define NC 1024
#define NH 128
#define NBT (NB*NT)

__device__ float g_Q[NBT*NH];
__device__ float g_K[NBT*NH];
__device__ float g_V[NBT*NH];

// ===========================================================================
// tf32 warp MMA helpers (sm_80+ PTX — no arch-specific 'a' features)
// ===========================================================================
__device__ __forceinline__ uint32_t f2tf(float x) {
    uint32_t r;
    asm("cvt.rna.tf32.f32 %0, %1;" : "=r"(r) : "f"(x));
    return r;
}
__device__ __forceinline__ void split_tf32(float x, uint32_t& hi, uint32_t& lo) {
    hi = f2tf(x);
    lo = f2tf(x - __uint_as_float(hi));
}
__device__ __forceinline__ void mma_tf32(float* d, const uint32_t* a, const uint32_t* b) {
    asm volatile(
        "mma.sync.aligned.m16n8k8.row.col.f32.tf32.tf32.f32 "
        "{%0,%1,%2,%3}, {%4,%5,%6,%7}, {%8,%9}, {%0,%1,%2,%3};"
        : "+f"(d[0]), "+f"(d[1]), "+f"(d[2]), "+f"(d[3])
        : "r"(a[0]), "r"(a[1]), "r"(a[2]), "r"(a[3]), "r"(b[0]), "r"(b[1]));
}

// ===========================================================================
// QKV projection (round-3 proven: ~53us, split-tf32 mma.sync)
// ===========================================================================
#define KC 32
#define APAD 36
#define STAGEF (2 * 128 * APAD)
#define QKV_SMEM (2 * STAGEF * 4)

__global__ __launch_bounds__(256, 1)
void qkv_mma_kernel(const float* __restrict__ x,
                    const float* __restrict__ Wq,
                    const float* __restrict__ Wk,
                    const float* __restrict__ Wv) {
    extern __shared__ float sm[];

    const float* __restrict__ W = (blockIdx.y == 0) ? Wq : (blockIdx.y == 1) ? Wk : Wv;
    float* out = (blockIdx.y == 0) ? g_Q : (blockIdx.y == 1) ? g_K : g_V;

    const int tid  = threadIdx.x;
    const int wid  = tid >> 5;
    const int lane = tid & 31;
    const int g    = lane >> 2;
    const int tig  = lane & 3;
    const int m0   = blockIdx.x * 128;

    const int r0 = tid >> 3;
    const int c4 = (tid & 7) * 4;
    const float* xb = x + (size_t)(m0 + r0) * NC + c4;
    const float* wb = W + (size_t)r0 * NC + c4;

    {
        float* As = sm;
        float* Bs = sm + 128 * APAD;
        #pragma unroll
        for (int it = 0; it < 4; it++) {
            *(float4*)&As[(r0 + 32*it) * APAD + c4] = *(const float4*)(xb + (size_t)(32*it) * NC);
            *(float4*)&Bs[(r0 + 32*it) * APAD + c4] = *(const float4*)(wb + (size_t)(32*it) * NC);
        }
    }
    __syncthreads();

    float acc[2][8][4];
    #pragma unroll
    for (int mf = 0; mf < 2; mf++)
        #pragma unroll
        for (int nf = 0; nf < 8; nf++)
            #pragma unroll
            for (int i = 0; i < 4; i++) acc[mf][nf][i] = 0.f;

    const int mrow = (wid & 3) * 32 + g;
    const int nbase = (wid >> 2) * 64 + g;

    for (int c = 0; c < NC / KC; c++) {
        const int st = c & 1;
        const float* As = sm + st * STAGEF;
        const float* Bs = As + 128 * APAD;

        float4 pa[4], pb[4];
        if (c < NC / KC - 1) {
            const int kn = (c + 1) * KC;
            #pragma unroll
            for (int it = 0; it < 4; it++) {
                pa[it] = *(const float4*)(xb + (size_t)(32*it) * NC + kn);
                pb[it] = *(const float4*)(wb + (size_t)(32*it) * NC + kn);
            }
        }

        #pragma unroll
        for (int kk = 0; kk < 4; kk++) {
            const int kc = kk * 8;
            uint32_t ahi[2][4], alo[2][4];
            #pragma unroll
            for (int mf = 0; mf < 2; mf++) {
                const int r = mrow + mf * 16;
                float v0 = As[r       * APAD + kc + tig];
                float v1 = As[(r + 8) * APAD + kc + tig];
                float v2 = As[r       * APAD + kc + tig + 4];
                float v3 = As[(r + 8) * APAD + kc + tig + 4];
                split_tf32(v0, ahi[mf][0], alo[mf][0]);
                split_tf32(v1, ahi[mf][1], alo[mf][1]);
                split_tf32(v2, ahi[mf][2], alo[mf][2]);
                split_tf32(v3, ahi[mf][3], alo[mf][3]);
            }
            #pragma unroll
            for (int nf = 0; nf < 8; nf++) {
                const int bc = nbase + nf * 8;
                float y0 = Bs[bc * APAD + kc + tig];
                float y1 = Bs[bc * APAD + kc + tig + 4];
                uint32_t bh[2], bl[2];
                split_tf32(y0, bh[0], bl[0]);
                split_tf32(y1, bh[1], bl[1]);
                #pragma unroll
                for (int mf = 0; mf < 2; mf++) {
                    mma_tf32(acc[mf][nf], ahi[mf], bh);
                    mma_tf32(acc[mf][nf], ahi[mf], bl);
                    mma_tf32(acc[mf][nf], alo[mf], bh);
                }
            }
        }

        if (c < NC / KC - 1) {
            float* Ad = sm + (st ^ 1) * STAGEF;
            float* Bd = Ad + 128 * APAD;
            #pragma unroll
            for (int it = 0; it < 4; it++) {
                *(float4*)&Ad[(r0 + 32*it) * APAD + c4] = pa[it];
                *(float4*)&Bd[(r0 + 32*it) * APAD + c4] = pb[it];
            }
        }
        __syncthreads();
    }

    #pragma unroll
    for (int mf = 0; mf < 2; mf++) {
        const int crow = m0 + mrow + mf * 16;
        #pragma unroll
        for (int nf = 0; nf < 8; nf++) {
            const int ccol = (wid >> 2) * 64 + nf * 8 + tig * 2;
            float2 v0 = make_float2(acc[mf][nf][0], acc[mf][nf][1]);
            float2 v1 = make_float2(acc[mf][nf][2], acc[mf][nf][3]);
            *(float2*)&out[(size_t)crow * NH + ccol]       = v0;
            *(float2*)&out[(size_t)(crow + 8) * NH + ccol] = v1;
        }
    }
}

// ===========================================================================
// Flash attention, 512 threads / CTA, 1 CTA/SM (16 warps, no reg cap spills).
// 64-row q tile, 64-row k/v tiles. Double-buffered K/V smem with register
// prefetch of the next tile. 2 barriers per iteration.
// PSTRP must be EVEN: PV pass reads float2 at j*PSTRP + ti (ti even).
// ===========================================================================
#define PSTR  68
#define PSTRP 66

#define OFF_QT  0
#define OFF_KT0 8704
#define OFF_KT1 17408
#define OFF_VS0 26112
#define OFF_VS1 34304
#define OFF_PT  42496
#define OFF_M   46724
#define OFF_L   46788
#define ATTN_SMEM (46852 * 4)

__global__ __launch_bounds__(512, 1)
void attn_kernel(float* __restrict__ out) {
    extern __shared__ float smf[];
    float* Qt  = smf + OFF_QT;
    float* Pt  = smf + OFF_PT;
    float* m_s = smf + OFF_M;
    float* l_s = smf + OFF_L;

    const int bid   = (int)blockIdx.x;
    const int qtile = 31 - (bid >> 3);        // longest work first
    const int b     = bid & 7;
    const int q0    = qtile * 64;

    const int tid = threadIdx.x;
    const int l16 = tid & 15;
    const int ti  = (tid >> 4) * 2;
    const int tj  = l16 * 4;
    const int tc0 = l16 * 4;
    const int tc1 = 64 + l16 * 4;

    const int lr = tid >> 5;
    const int ld4 = (tid & 31) * 4;

    const float* Qg = g_Q + ((size_t)b * NT + q0) * NH;
    #pragma unroll
    for (int it = 0; it < 4; it++) {
        int r = lr + it * 16;
        float4 v = *(const float4*)&Qg[r * NH + ld4];
        Qt[(ld4+0)*PSTR + r] = v.x;
        Qt[(ld4+1)*PSTR + r] = v.y;
        Qt[(ld4+2)*PSTR + r] = v.z;
        Qt[(ld4+3)*PSTR + r] = v.w;
    }

    const float* Kg = g_K + (size_t)b * NT * NH;
    const float* Vg = g_V + (size_t)b * NT * NH;

    {
        float* Kd = smf + OFF_KT0;
        float* Vd = smf + OFF_VS0;
        #pragma unroll
        for (int it = 0; it < 4; it++) {
            int r = lr + it * 16;
            float4 v = *(const float4*)&Kg[r * NH + ld4];
            Kd[(ld4+0)*PSTR + r] = v.x;
            Kd[(ld4+1)*PSTR + r] = v.y;
            Kd[(ld4+2)*PSTR + r] = v.z;
            Kd[(ld4+3)*PSTR + r] = v.w;
            float4 w = *(const float4*)&Vg[r * NH + ld4];
            *(float4*)&Vd[r * NH + ld4] = w;
        }
    }
    if (tid < 64) { m_s[tid] = -INFINITY; l_s[tid] = 0.f; }

    float acc[2][8];
    #pragma unroll
    for (int i = 0; i < 2; i++)
        #pragma unroll
        for (int j = 0; j < 8; j++) acc[i][j] = 0.f;

    const float scale = 0.08838834764831845f;
    __syncthreads();

    for (int kt = 0; kt <= qtile; kt++) {
        const int cur = kt & 1;
        const float* Ktc = smf + (cur ? OFF_KT1 : OFF_KT0);
        const float* Vsc = smf + (cur ? OFF_VS1 : OFF_VS0);

        const bool pre = (kt < qtile);
        float4 pk[4], pv[4];
        if (pre) {
            const float* Kn = Kg + (size_t)(kt + 1) * 64 * NH;
            const float* Vn = Vg + (size_t)(kt + 1) * 64 * NH;
            #pragma unroll
            for (int it = 0; it < 4; it++) {
                int r = lr + it * 16;
                pk[it] = *(const float4*)&Kn[r * NH + ld4];
                pv[it] = *(const float4*)&Vn[r * NH + ld4];
            }
        }

        float s[2][4];
        #pragma unroll
        for (int i = 0; i < 2; i++)
            #pragma unroll
            for (int j = 0; j < 4; j++) s[i][j] = 0.f;

        #pragma unroll 8
        for (int d = 0; d < 128; d++) {
            float2 aq = *(const float2*)&Qt[d * PSTR + ti];
            float4 bk = *(const float4*)&Ktc[d * PSTR + tj];
            float av[2] = {aq.x, aq.y};
            float bv[4] = {bk.x, bk.y, bk.z, bk.w};
            #pragma unroll
            for (int i = 0; i < 2; i++)
                #pragma unroll
                for (int j = 0; j < 4; j++)
                    s[i][j] += av[i] * bv[j];
        }

        const bool diag = (kt == qtile);
        float alpha[2];
        #pragma unroll
        for (int ii = 0; ii < 2; ii++) {
            float rmax = -INFINITY;
            #pragma unroll
            for (int jj = 0; jj < 4; jj++) {
                float sv = s[ii][jj] * scale;
                if (diag && (tj + jj > ti + ii)) sv = -INFINITY;
                s[ii][jj] = sv;
                rmax = fmaxf(rmax, sv);
            }
            #pragma unroll
            for (int off = 8; off > 0; off >>= 1)
                rmax = fmaxf(rmax, __shfl_xor_sync(0xffffffffu, rmax, off, 16));
            float mold = m_s[ti + ii];
            float mnew = fmaxf(mold, rmax);
            float a_ = (mold == -INFINITY) ? 0.f : __expf(mold - mnew);
            alpha[ii] = a_;
            float rsum = 0.f;
            #pragma unroll
            for (int jj = 0; jj < 4; jj++) {
                float p = __expf(s[ii][jj] - mnew);
                s[ii][jj] = p;
                rsum += p;
            }
            #pragma unroll
            for (int off = 8; off > 0; off >>= 1)
                rsum += __shfl_xor_sync(0xffffffffu, rsum, off, 16);
            if (l16 == 0) {
                m_s[ti + ii] = mnew;
                l_s[ti + ii] = l_s[ti + ii] * a_ + rsum;
            }
        }

        __syncthreads();   // A: prev PV reads of Pt/Vs done

        if (pre) {
            float* Kd = smf + (cur ? OFF_KT0 : OFF_KT1);
            float* Vd = smf + (cur ? OFF_VS0 : OFF_VS1);
            #pragma unroll
            for (int it = 0; it < 4; it++) {
                int r = lr + it * 16;
                Kd[(ld4+0)*PSTR + r] = pk[it].x;
                Kd[(ld4+1)*PSTR + r] = pk[it].y;
                Kd[(ld4+2)*PSTR + r] = pk[it].z;
                Kd[(ld4+3)*PSTR + r] = pk[it].w;
                *(float4*)&Vd[r * NH + ld4] = pv[it];
            }
        }

        // P to smem (transposed): one float2 per (row-pair, col)
        #pragma unroll
        for (int jj = 0; jj < 4; jj++)
            *(float2*)&Pt[(tj + jj) * PSTRP + ti] = make_float2(s[0][jj], s[1][jj]);

        #pragma unroll
        for (int ii = 0; ii < 2; ii++)
            #pragma unroll
            for (int cc = 0; cc < 8; cc++)
                acc[ii][cc] *= alpha[ii];

        __syncthreads();   // B: Pt + next tile visible

        #pragma unroll 4
        for (int j = 0; j < 64; j++) {
            float2 p2 = *(const float2*)&Pt[j * PSTRP + ti];
            float4 v0 = *(const float4*)&Vsc[j * NH + tc0];
            float4 v1 = *(const float4*)&Vsc[j * NH + tc1];
            float pv_[2] = {p2.x, p2.y};
            float vv[8] = {v0.x, v0.y, v0.z, v0.w, v1.x, v1.y, v1.z, v1.w};
            #pragma unroll
            for (int ii = 0; ii < 2; ii++)
                #pragma unroll
                for (int cc = 0; cc < 8; cc++)
                    acc[ii][cc] += pv_[ii] * vv[cc];
        }
    }

    float* Og = out + ((size_t)b * NT + q0) * NH;
    #pragma unroll
    for (int ii = 0; ii < 2; ii++) {
        float inv = 1.f / l_s[ti + ii];
        float4 o0 = make_float4(acc[ii][0]*inv, acc[ii][1]*inv, acc[ii][2]*inv, acc[ii][3]*inv);
        float4 o1 = make_float4(acc[ii][4]*inv, acc[ii][5]*inv, acc[ii][6]*inv, acc[ii][7]*inv);
        *(float4*)&Og[(ti + ii) * NH + tc0] = o0;
        *(float4*)&Og[(ti + ii) * NH + tc1] = o1;
    }
}

// ---------------------------------------------------------------------------
extern "C" void kernel_launch(void* const* d_in, const int* in_sizes, int n_in,
                              void* d_out, int out_size) {
    const float* x  = (const float*)d_in[0];
    const float* Wq = (const float*)d_in[1];
    const float* Wk = (const float*)d_in[2];
    const float* Wv = (const float*)d_in[3];
    float* out = (float*)d_out;

    cudaFuncSetAttribute(qkv_mma_kernel,
                         cudaFuncAttributeMaxDynamicSharedMemorySize, QKV_SMEM);
    qkv_mma_kernel<<<dim3(NBT / 128, 3), 256, QKV_SMEM>>>(x, Wq, Wk, Wv);

    cudaFuncSetAttribute(attn_kernel,
                         cudaFuncAttributeMaxDynamicSharedMemorySize, ATTN_SMEM);
    attn_kernel<<<256, 512, ATTN_SMEM>>>(out);
}

// round 7
// speedup vs baseline: 1.5266x; 1.5266x over previous
#include <cuda_runtime.h>
#include <math.h>
#include <stdint.h>

#define NB 8
#define NT 2048
#define NC 1024
#define NH 128
#define NBT (NB*NT)

__device__ float g_Q[NBT*NH];
__device__ float g_K[NBT*NH];
__device__ float g_V[NBT*NH];

// ===========================================================================
// tf32 warp MMA helpers (sm_80+ PTX — no arch-specific 'a' features)
// ===========================================================================
__device__ __forceinline__ uint32_t f2tf(float x) {
    uint32_t r;
    asm("cvt.rna.tf32.f32 %0, %1;" : "=r"(r) : "f"(x));
    return r;
}
__device__ __forceinline__ void split_tf32(float x, uint32_t& hi, uint32_t& lo) {
    hi = f2tf(x);
    lo = f2tf(x - __uint_as_float(hi));
}
__device__ __forceinline__ void mma_tf32(float* d, const uint32_t* a, const uint32_t* b) {
    asm volatile(
        "mma.sync.aligned.m16n8k8.row.col.f32.tf32.tf32.f32 "
        "{%0,%1,%2,%3}, {%4,%5,%6,%7}, {%8,%9}, {%0,%1,%2,%3};"
        : "+f"(d[0]), "+f"(d[1]), "+f"(d[2]), "+f"(d[3])
        : "r"(a[0]), "r"(a[1]), "r"(a[2]), "r"(a[3]), "r"(b[0]), "r"(b[1]));
}

// ===========================================================================
// QKV projection (round-3 proven: ~53us, split-tf32 mma.sync)
// ===========================================================================
#define KC 32
#define APAD 36
#define STAGEF (2 * 128 * APAD)
#define QKV_SMEM (2 * STAGEF * 4)

__global__ __launch_bounds__(256, 1)
void qkv_mma_kernel(const float* __restrict__ x,
                    const float* __restrict__ Wq,
                    const float* __restrict__ Wk,
                    const float* __restrict__ Wv) {
    extern __shared__ float sm[];

    const float* __restrict__ W = (blockIdx.y == 0) ? Wq : (blockIdx.y == 1) ? Wk : Wv;
    float* out = (blockIdx.y == 0) ? g_Q : (blockIdx.y == 1) ? g_K : g_V;

    const int tid  = threadIdx.x;
    const int wid  = tid >> 5;
    const int lane = tid & 31;
    const int g    = lane >> 2;
    const int tig  = lane & 3;
    const int m0   = blockIdx.x * 128;

    const int r0 = tid >> 3;
    const int c4 = (tid & 7) * 4;
    const float* xb = x + (size_t)(m0 + r0) * NC + c4;
    const float* wb = W + (size_t)r0 * NC + c4;

    {
        float* As = sm;
        float* Bs = sm + 128 * APAD;
        #pragma unroll
        for (int it = 0; it < 4; it++) {
            *(float4*)&As[(r0 + 32*it) * APAD + c4] = *(const float4*)(xb + (size_t)(32*it) * NC);
            *(float4*)&Bs[(r0 + 32*it) * APAD + c4] = *(const float4*)(wb + (size_t)(32*it) * NC);
        }
    }
    __syncthreads();

    float acc[2][8][4];
    #pragma unroll
    for (int mf = 0; mf < 2; mf++)
        #pragma unroll
        for (int nf = 0; nf < 8; nf++)
            #pragma unroll
            for (int i = 0; i < 4; i++) acc[mf][nf][i] = 0.f;

    const int mrow = (wid & 3) * 32 + g;
    const int nbase = (wid >> 2) * 64 + g;

    for (int c = 0; c < NC / KC; c++) {
        const int st = c & 1;
        const float* As = sm + st * STAGEF;
        const float* Bs = As + 128 * APAD;

        float4 pa[4], pb[4];
        if (c < NC / KC - 1) {
            const int kn = (c + 1) * KC;
            #pragma unroll
            for (int it = 0; it < 4; it++) {
                pa[it] = *(const float4*)(xb + (size_t)(32*it) * NC + kn);
                pb[it] = *(const float4*)(wb + (size_t)(32*it) * NC + kn);
            }
        }

        #pragma unroll
        for (int kk = 0; kk < 4; kk++) {
            const int kc = kk * 8;
            uint32_t ahi[2][4], alo[2][4];
            #pragma unroll
            for (int mf = 0; mf < 2; mf++) {
                const int r = mrow + mf * 16;
                float v0 = As[r       * APAD + kc + tig];
                float v1 = As[(r + 8) * APAD + kc + tig];
                float v2 = As[r       * APAD + kc + tig + 4];
                float v3 = As[(r + 8) * APAD + kc + tig + 4];
                split_tf32(v0, ahi[mf][0], alo[mf][0]);
                split_tf32(v1, ahi[mf][1], alo[mf][1]);
                split_tf32(v2, ahi[mf][2], alo[mf][2]);
                split_tf32(v3, ahi[mf][3], alo[mf][3]);
            }
            #pragma unroll
            for (int nf = 0; nf < 8; nf++) {
                const int bc = nbase + nf * 8;
                float y0 = Bs[bc * APAD + kc + tig];
                float y1 = Bs[bc * APAD + kc + tig + 4];
                uint32_t bh[2], bl[2];
                split_tf32(y0, bh[0], bl[0]);
                split_tf32(y1, bh[1], bl[1]);
                #pragma unroll
                for (int mf = 0; mf < 2; mf++) {
                    mma_tf32(acc[mf][nf], ahi[mf], bh);
                    mma_tf32(acc[mf][nf], ahi[mf], bl);
                    mma_tf32(acc[mf][nf], alo[mf], bh);
                }
            }
        }

        if (c < NC / KC - 1) {
            float* Ad = sm + (st ^ 1) * STAGEF;
            float* Bd = Ad + 128 * APAD;
            #pragma unroll
            for (int it = 0; it < 4; it++) {
                *(float4*)&Ad[(r0 + 32*it) * APAD + c4] = pa[it];
                *(float4*)&Bd[(r0 + 32*it) * APAD + c4] = pb[it];
            }
        }
        __syncthreads();
    }

    #pragma unroll
    for (int mf = 0; mf < 2; mf++) {
        const int crow = m0 + mrow + mf * 16;
        #pragma unroll
        for (int nf = 0; nf < 8; nf++) {
            const int ccol = (wid >> 2) * 64 + nf * 8 + tig * 2;
            float2 v0 = make_float2(acc[mf][nf][0], acc[mf][nf][1]);
            float2 v1 = make_float2(acc[mf][nf][2], acc[mf][nf][3]);
            *(float2*)&out[(size_t)crow * NH + ccol]       = v0;
            *(float2*)&out[(size_t)(crow + 8) * NH + ccol] = v1;
        }
    }
}

// ===========================================================================
// Flash attention, 512 threads / CTA, 1 CTA/SM (16 warps, no reg cap spills).
// 64-row q tile, 64-row k/v tiles. Double-buffered K/V smem with register
// prefetch of the next tile. 2 barriers per iteration.
// PSTRP must be EVEN: PV pass reads float2 at j*PSTRP + ti (ti even).
// ===========================================================================
#define PSTR  68
#define PSTRP 66

#define OFF_QT  0
#define OFF_KT0 8704
#define OFF_KT1 17408
#define OFF_VS0 26112
#define OFF_VS1 34304
#define OFF_PT  42496
#define OFF_M   46724
#define OFF_L   46788
#define ATTN_SMEM (46852 * 4)

__global__ __launch_bounds__(512, 1)
void attn_kernel(float* __restrict__ out) {
    extern __shared__ float smf[];
    float* Qt  = smf + OFF_QT;
    float* Pt  = smf + OFF_PT;
    float* m_s = smf + OFF_M;
    float* l_s = smf + OFF_L;

    const int bid   = (int)blockIdx.x;
    const int qtile = 31 - (bid >> 3);        // longest work first
    const int b     = bid & 7;
    const int q0    = qtile * 64;

    const int tid = threadIdx.x;
    const int l16 = tid & 15;
    const int ti  = (tid >> 4) * 2;
    const int tj  = l16 * 4;
    const int tc0 = l16 * 4;
    const int tc1 = 64 + l16 * 4;

    const int lr = tid >> 5;
    const int ld4 = (tid & 31) * 4;

    const float* Qg = g_Q + ((size_t)b * NT + q0) * NH;
    #pragma unroll
    for (int it = 0; it < 4; it++) {
        int r = lr + it * 16;
        float4 v = *(const float4*)&Qg[r * NH + ld4];
        Qt[(ld4+0)*PSTR + r] = v.x;
        Qt[(ld4+1)*PSTR + r] = v.y;
        Qt[(ld4+2)*PSTR + r] = v.z;
        Qt[(ld4+3)*PSTR + r] = v.w;
    }

    const float* Kg = g_K + (size_t)b * NT * NH;
    const float* Vg = g_V + (size_t)b * NT * NH;

    {
        float* Kd = smf + OFF_KT0;
        float* Vd = smf + OFF_VS0;
        #pragma unroll
        for (int it = 0; it < 4; it++) {
            int r = lr + it * 16;
            float4 v = *(const float4*)&Kg[r * NH + ld4];
            Kd[(ld4+0)*PSTR + r] = v.x;
            Kd[(ld4+1)*PSTR + r] = v.y;
            Kd[(ld4+2)*PSTR + r] = v.z;
            Kd[(ld4+3)*PSTR + r] = v.w;
            float4 w = *(const float4*)&Vg[r * NH + ld4];
            *(float4*)&Vd[r * NH + ld4] = w;
        }
    }
    if (tid < 64) { m_s[tid] = -INFINITY; l_s[tid] = 0.f; }

    float acc[2][8];
    #pragma unroll
    for (int i = 0; i < 2; i++)
        #pragma unroll
        for (int j = 0; j < 8; j++) acc[i][j] = 0.f;

    const float scale = 0.08838834764831845f;
    __syncthreads();

    for (int kt = 0; kt <= qtile; kt++) {
        const int cur = kt & 1;
        const float* Ktc = smf + (cur ? OFF_KT1 : OFF_KT0);
        const float* Vsc = smf + (cur ? OFF_VS1 : OFF_VS0);

        const bool pre = (kt < qtile);
        float4 pk[4], pv[4];
        if (pre) {
            const float* Kn = Kg + (size_t)(kt + 1) * 64 * NH;
            const float* Vn = Vg + (size_t)(kt + 1) * 64 * NH;
            #pragma unroll
            for (int it = 0; it < 4; it++) {
                int r = lr + it * 16;
                pk[it] = *(const float4*)&Kn[r * NH + ld4];
                pv[it] = *(const float4*)&Vn[r * NH + ld4];
            }
        }

        float s[2][4];
        #pragma unroll
        for (int i = 0; i < 2; i++)
            #pragma unroll
            for (int j = 0; j < 4; j++) s[i][j] = 0.f;

        #pragma unroll 8
        for (int d = 0; d < 128; d++) {
            float2 aq = *(const float2*)&Qt[d * PSTR + ti];
            float4 bk = *(const float4*)&Ktc[d * PSTR + tj];
            float av[2] = {aq.x, aq.y};
            float bv[4] = {bk.x, bk.y, bk.z, bk.w};
            #pragma unroll
            for (int i = 0; i < 2; i++)
                #pragma unroll
                for (int j = 0; j < 4; j++)
                    s[i][j] += av[i] * bv[j];
        }

        const bool diag = (kt == qtile);
        float alpha[2];
        #pragma unroll
        for (int ii = 0; ii < 2; ii++) {
            float rmax = -INFINITY;
            #pragma unroll
            for (int jj = 0; jj < 4; jj++) {
                float sv = s[ii][jj] * scale;
                if (diag && (tj + jj > ti + ii)) sv = -INFINITY;
                s[ii][jj] = sv;
                rmax = fmaxf(rmax, sv);
            }
            #pragma unroll
            for (int off = 8; off > 0; off >>= 1)
                rmax = fmaxf(rmax, __shfl_xor_sync(0xffffffffu, rmax, off, 16));
            float mold = m_s[ti + ii];
            float mnew = fmaxf(mold, rmax);
            float a_ = (mold == -INFINITY) ? 0.f : __expf(mold - mnew);
            alpha[ii] = a_;
            float rsum = 0.f;
            #pragma unroll
            for (int jj = 0; jj < 4; jj++) {
                float p = __expf(s[ii][jj] - mnew);
                s[ii][jj] = p;
                rsum += p;
            }
            #pragma unroll
            for (int off = 8; off > 0; off >>= 1)
                rsum += __shfl_xor_sync(0xffffffffu, rsum, off, 16);
            if (l16 == 0) {
                m_s[ti + ii] = mnew;
                l_s[ti + ii] = l_s[ti + ii] * a_ + rsum;
            }
        }

        __syncthreads();   // A: prev PV reads of Pt/Vs done

        if (pre) {
            float* Kd = smf + (cur ? OFF_KT0 : OFF_KT1);
            float* Vd = smf + (cur ? OFF_VS0 : OFF_VS1);
            #pragma unroll
            for (int it = 0; it < 4; it++) {
                int r = lr + it * 16;
                Kd[(ld4+0)*PSTR + r] = pk[it].x;
                Kd[(ld4+1)*PSTR + r] = pk[it].y;
                Kd[(ld4+2)*PSTR + r] = pk[it].z;
                Kd[(ld4+3)*PSTR + r] = pk[it].w;
                *(float4*)&Vd[r * NH + ld4] = pv[it];
            }
        }

        // P to smem (transposed): one float2 per (row-pair, col)
        #pragma unroll
        for (int jj = 0; jj < 4; jj++)
            *(float2*)&Pt[(tj + jj) * PSTRP + ti] = make_float2(s[0][jj], s[1][jj]);

        #pragma unroll
        for (int ii = 0; ii < 2; ii++)
            #pragma unroll
            for (int cc = 0; cc < 8; cc++)
                acc[ii][cc] *= alpha[ii];

        __syncthreads();   // B: Pt + next tile visible

        #pragma unroll 4
        for (int j = 0; j < 64; j++) {
            float2 p2 = *(const float2*)&Pt[j * PSTRP + ti];
            float4 v0 = *(const float4*)&Vsc[j * NH + tc0];
            float4 v1 = *(const float4*)&Vsc[j * NH + tc1];
            float pv_[2] = {p2.x, p2.y};
            float vv[8] = {v0.x, v0.y, v0.z, v0.w, v1.x, v1.y, v1.z, v1.w};
            #pragma unroll
            for (int ii = 0; ii < 2; ii++)
                #pragma unroll
                for (int cc = 0; cc < 8; cc++)
                    acc[ii][cc] += pv_[ii] * vv[cc];
        }
    }

    float* Og = out + ((size_t)b * NT + q0) * NH;
    #pragma unroll
    for (int ii = 0; ii < 2; ii++) {
        float inv = 1.f / l_s[ti + ii];
        float4 o0 = make_float4(acc[ii][0]*inv, acc[ii][1]*inv, acc[ii][2]*inv, acc[ii][3]*inv);
        float4 o1 = make_float4(acc[ii][4]*inv, acc[ii][5]*inv, acc[ii][6]*inv, acc[ii][7]*inv);
        *(float4*)&Og[(ti + ii) * NH + tc0] = o0;
        *(float4*)&Og[(ti + ii) * NH + tc1] = o1;
    }
}

// ---------------------------------------------------------------------------
extern "C" void kernel_launch(void* const* d_in, const int* in_sizes, int n_in,
                              void* d_out, int out_size) {
    const float* x  = (const float*)d_in[0];
    const float* Wq = (const float*)d_in[1];
    const float* Wk = (const float*)d_in[2];
    const float* Wv = (const float*)d_in[3];
    float* out = (float*)d_out;

    cudaFuncSetAttribute(qkv_mma_kernel,
                         cudaFuncAttributeMaxDynamicSharedMemorySize, QKV_SMEM);
    qkv_mma_kernel<<<dim3(NBT / 128, 3), 256, QKV_SMEM>>>(x, Wq, Wk, Wv);

    cudaFuncSetAttribute(attn_kernel,
                         cudaFuncAttributeMaxDynamicSharedMemorySize, ATTN_SMEM);
    attn_kernel<<<256, 512, ATTN_SMEM>>>(out);
}

// round 9
// speedup vs baseline: 2.6673x; 1.7471x over previous
#include <cuda_runtime.h>
#include <cuda_bf16.h>
#include <math.h>
#include <stdint.h>

#define NB 8
#define NT 2048
#define NC 1024
#define NH 128
#define NBT (NB*NT)

// bf16 hi/lo split scratch produced by qkv kernel
__device__ __nv_bfloat16 g_Qh[NBT*NH];   // Q * scale, [b][t][d]
__device__ __nv_bfloat16 g_Ql[NBT*NH];
__device__ __nv_bfloat16 g_Kh[NBT*NH];   // [b][t][d]
__device__ __nv_bfloat16 g_Kl[NBT*NH];
__device__ __nv_bfloat16 g_Vth[NB*NH*NT]; // transposed: [b][d][t]
__device__ __nv_bfloat16 g_Vtl[NB*NH*NT];

// ===========================================================================
// MMA helpers (generic sm_80+ PTX)
// ===========================================================================
__device__ __forceinline__ uint32_t f2tf(float x) {
    uint32_t r;
    asm("cvt.rna.tf32.f32 %0, %1;" : "=r"(r) : "f"(x));
    return r;
}
__device__ __forceinline__ void split_tf32(float x, uint32_t& hi, uint32_t& lo) {
    hi = f2tf(x);
    lo = f2tf(x - __uint_as_float(hi));
}
__device__ __forceinline__ void mma_tf32(float* d, const uint32_t* a, const uint32_t* b) {
    asm volatile(
        "mma.sync.aligned.m16n8k8.row.col.f32.tf32.tf32.f32 "
        "{%0,%1,%2,%3}, {%4,%5,%6,%7}, {%8,%9}, {%0,%1,%2,%3};"
        : "+f"(d[0]), "+f"(d[1]), "+f"(d[2]), "+f"(d[3])
        : "r"(a[0]), "r"(a[1]), "r"(a[2]), "r"(a[3]), "r"(b[0]), "r"(b[1]));
}
__device__ __forceinline__ void mma_bf16(float* d, const uint32_t* a, const uint32_t* b) {
    asm volatile(
        "mma.sync.aligned.m16n8k16.row.col.f32.bf16.bf16.f32 "
        "{%0,%1,%2,%3}, {%4,%5,%6,%7}, {%8,%9}, {%0,%1,%2,%3};"
        : "+f"(d[0]), "+f"(d[1]), "+f"(d[2]), "+f"(d[3])
        : "r"(a[0]), "r"(a[1]), "r"(a[2]), "r"(a[3]), "r"(b[0]), "r"(b[1]));
}
__device__ __forceinline__ void bsplit2(float x, float y, uint32_t& h, uint32_t& l) {
    __nv_bfloat162 hh = __floats2bfloat162_rn(x, y);
    float rx = x - __bfloat162float(hh.x);
    float ry = y - __bfloat162float(hh.y);
    __nv_bfloat162 ll = __floats2bfloat162_rn(rx, ry);
    h = *(uint32_t*)&hh;
    l = *(uint32_t*)&ll;
}
__device__ __forceinline__ uint32_t smem_u32(const void* p) {
    uint32_t a;
    asm("{ .reg .u64 t; cvta.to.shared.u64 t, %1; cvt.u32.u64 %0, t; }" : "=r"(a) : "l"(p));
    return a;
}
#define CPA16(dst, src) \
    asm volatile("cp.async.cg.shared.global [%0], [%1], 16;" :: "r"(dst), "l"(src))
#define CP_COMMIT asm volatile("cp.async.commit_group;" ::: "memory")
#define CP_WAIT(n) asm volatile("cp.async.wait_group %0;" :: "n"(n) : "memory")

// ===========================================================================
// QKV projection (split-tf32 mma.sync core, proven). Epilogue emits
// bf16 hi/lo: Q (pre-scaled), K row-major; V transposed [d][t] via smem.
// ===========================================================================
#define KC 32
#define APAD 36
#define STAGEF (2 * 128 * APAD)
#define QKV_SMEM (2 * STAGEF * 4)

__global__ __launch_bounds__(256, 1)
void qkv_mma_kernel(const float* __restrict__ x,
                    const float* __restrict__ Wq,
                    const float* __restrict__ Wk,
                    const float* __restrict__ Wv) {
    extern __shared__ float sm[];

    const float* __restrict__ W = (blockIdx.y == 0) ? Wq : (blockIdx.y == 1) ? Wk : Wv;

    const int tid  = threadIdx.x;
    const int wid  = tid >> 5;
    const int lane = tid & 31;
    const int g    = lane >> 2;
    const int tig  = lane & 3;
    const int m0   = blockIdx.x * 128;

    const int r0 = tid >> 3;
    const int c4 = (tid & 7) * 4;
    const float* xb = x + (size_t)(m0 + r0) * NC + c4;
    const float* wb = W + (size_t)r0 * NC + c4;

    {
        float* As = sm;
        float* Bs = sm + 128 * APAD;
        #pragma unroll
        for (int it = 0; it < 4; it++) {
            *(float4*)&As[(r0 + 32*it) * APAD + c4] = *(const float4*)(xb + (size_t)(32*it) * NC);
            *(float4*)&Bs[(r0 + 32*it) * APAD + c4] = *(const float4*)(wb + (size_t)(32*it) * NC);
        }
    }
    __syncthreads();

    float acc[2][8][4];
    #pragma unroll
    for (int mf = 0; mf < 2; mf++)
        #pragma unroll
        for (int nf = 0; nf < 8; nf++)
            #pragma unroll
            for (int i = 0; i < 4; i++) acc[mf][nf][i] = 0.f;

    const int mrow = (wid & 3) * 32 + g;
    const int nbase = (wid >> 2) * 64 + g;

    for (int c = 0; c < NC / KC; c++) {
        const int st = c & 1;
        const float* As = sm + st * STAGEF;
        const float* Bs = As + 128 * APAD;

        float4 pa[4], pb[4];
        if (c < NC / KC - 1) {
            const int kn = (c + 1) * KC;
            #pragma unroll
            for (int it = 0; it < 4; it++) {
                pa[it] = *(const float4*)(xb + (size_t)(32*it) * NC + kn);
                pb[it] = *(const float4*)(wb + (size_t)(32*it) * NC + kn);
            }
        }

        #pragma unroll
        for (int kk = 0; kk < 4; kk++) {
            const int kc = kk * 8;
            uint32_t ahi[2][4], alo[2][4];
            #pragma unroll
            for (int mf = 0; mf < 2; mf++) {
                const int r = mrow + mf * 16;
                float v0 = As[r       * APAD + kc + tig];
                float v1 = As[(r + 8) * APAD + kc + tig];
                float v2 = As[r       * APAD + kc + tig + 4];
                float v3 = As[(r + 8) * APAD + kc + tig + 4];
                split_tf32(v0, ahi[mf][0], alo[mf][0]);
                split_tf32(v1, ahi[mf][1], alo[mf][1]);
                split_tf32(v2, ahi[mf][2], alo[mf][2]);
                split_tf32(v3, ahi[mf][3], alo[mf][3]);
            }
            #pragma unroll
            for (int nf = 0; nf < 8; nf++) {
                const int bc = nbase + nf * 8;
                float y0 = Bs[bc * APAD + kc + tig];
                float y1 = Bs[bc * APAD + kc + tig + 4];
                uint32_t bh[2], bl[2];
                split_tf32(y0, bh[0], bl[0]);
                split_tf32(y1, bh[1], bl[1]);
                #pragma unroll
                for (int mf = 0; mf < 2; mf++) {
                    mma_tf32(acc[mf][nf], ahi[mf], bh);
                    mma_tf32(acc[mf][nf], ahi[mf], bl);
                    mma_tf32(acc[mf][nf], alo[mf], bh);
                }
            }
        }

        if (c < NC / KC - 1) {
            float* Ad = sm + (st ^ 1) * STAGEF;
            float* Bd = Ad + 128 * APAD;
            #pragma unroll
            for (int it = 0; it < 4; it++) {
                *(float4*)&Ad[(r0 + 32*it) * APAD + c4] = pa[it];
                *(float4*)&Bd[(r0 + 32*it) * APAD + c4] = pb[it];
            }
        }
        __syncthreads();
    }

    // ---- epilogue: bf16 hi/lo ----
    if (blockIdx.y < 2) {
        __nv_bfloat16* oh = (blockIdx.y == 0) ? g_Qh : g_Kh;
        __nv_bfloat16* ol = (blockIdx.y == 0) ? g_Ql : g_Kl;
        const float sc = (blockIdx.y == 0) ? 0.08838834764831845f : 1.0f;
        #pragma unroll
        for (int mf = 0; mf < 2; mf++) {
            const int crow = m0 + mrow + mf * 16;
            #pragma unroll
            for (int nf = 0; nf < 8; nf++) {
                const int ccol = (wid >> 2) * 64 + nf * 8 + tig * 2;
                uint32_t h01, l01, h23, l23;
                bsplit2(acc[mf][nf][0]*sc, acc[mf][nf][1]*sc, h01, l01);
                bsplit2(acc[mf][nf][2]*sc, acc[mf][nf][3]*sc, h23, l23);
                *(uint32_t*)&oh[(size_t)crow * NH + ccol]       = h01;
                *(uint32_t*)&ol[(size_t)crow * NH + ccol]       = l01;
                *(uint32_t*)&oh[(size_t)(crow + 8) * NH + ccol] = h23;
                *(uint32_t*)&ol[(size_t)(crow + 8) * NH + ccol] = l23;
            }
        }
    } else {
        // V: transpose to [d][t] via smem, then coalesced writes
        __nv_bfloat16* svh = (__nv_bfloat16*)sm;       // [128 d][136]
        __nv_bfloat16* svl = svh + 128 * 136;
        #pragma unroll
        for (int mf = 0; mf < 2; mf++) {
            const int rl = mrow + mf * 16;   // local 0..127
            #pragma unroll
            for (int nf = 0; nf < 8; nf++) {
                const int ccol = (wid >> 2) * 64 + nf * 8 + tig * 2;
                #pragma unroll
                for (int e = 0; e < 4; e++) {
                    float a = acc[mf][nf][e];
                    int d = ccol + (e & 1);
                    int m = rl + (e >> 1) * 8;
                    __nv_bfloat16 h = __float2bfloat16(a);
                    __nv_bfloat16 l = __float2bfloat16(a - __bfloat162float(h));
                    svh[d * 136 + m] = h;
                    svl[d * 136 + m] = l;
                }
            }
        }
        __syncthreads();
        const int b  = m0 >> 11;
        const int t0 = m0 & 2047;
        #pragma unroll
        for (int i = 0; i < 16; i++) {
            int c = tid + i * 256;          // 4096 chunks of 16B
            int cc = c & 2047;
            int d = cc >> 4, col = cc & 15;
            const __nv_bfloat16* src = (c < 2048 ? svh : svl) + d * 136 + col * 8;
            __nv_bfloat16* dst = (c < 2048 ? g_Vth : g_Vtl)
                                 + ((size_t)b * NH + d) * NT + t0 + col * 8;
            *(float4*)dst = *(const float4*)src;
        }
    }
}

// ===========================================================================
// Flash attention with mma.sync bf16 split (3 MMAs per logical GEMM).
// CTA: 128 threads, 4 warps, 64 q-rows (warp = 16-row band), k-tile 32.
// Q/K/V in bf16 hi/lo smem; cp.async double-buffered K and V stages.
// P stays in registers (S c-frag == PV A-frag layout). m/l in registers.
// ===========================================================================
#define ATTN_SMEM 110592

__device__ __forceinline__ void load_K_tile(uint32_t sb, int b, int kt, int st, int tid) {
    const __nv_bfloat16* kh = g_Kh + ((size_t)b * NT + kt * 32) * NH;
    const __nv_bfloat16* kl = g_Kl + ((size_t)b * NT + kt * 32) * NH;
    uint32_t base = sb + 34816u + (uint32_t)st * 17408u;
    #pragma unroll
    for (int i = 0; i < 8; i++) {
        int c = tid + i * 128;
        int cc = c & 511;
        int row = cc >> 4, col = cc & 15;
        const __nv_bfloat16* src = (c < 512 ? kh : kl) + row * NH + col * 8;
        uint32_t dst = base + (c < 512 ? 0u : 8704u) + row * 272 + col * 16;
        CPA16(dst, src);
    }
}
__device__ __forceinline__ void load_V_tile(uint32_t sb, int b, int kt, int st, int tid) {
    const __nv_bfloat16* vh = g_Vth + (size_t)b * NH * NT + kt * 32;
    const __nv_bfloat16* vl = g_Vtl + (size_t)b * NH * NT + kt * 32;
    uint32_t base = sb + 69632u + (uint32_t)st * 20480u;
    #pragma unroll
    for (int i = 0; i < 8; i++) {
        int c = tid + i * 128;
        int cc = c & 511;
        int row = cc >> 2, col = cc & 3;
        const __nv_bfloat16* src = (c < 512 ? vh : vl) + (size_t)row * NT + col * 8;
        uint32_t dst = base + (c < 512 ? 0u : 10240u) + row * 80 + col * 16;
        CPA16(dst, src);
    }
}

__global__ __launch_bounds__(128, 2)
void attn_kernel(float* __restrict__ out) {
    extern __shared__ char smc[];
    const uint32_t sb = smem_u32(smc);

    // Exact-cover balanced mapping (each (qtile,b) once):
    //   bid 0..103   -> qtiles 0..12        (pairs with bid+148)
    //   bid 104..107 -> qtile 13, b 0..3    (pairs with bid+148 = b 4..7)
    //   bid 108..147 -> qtiles 27..31 (solo SMs)
    //   bid 148..251 -> qtiles 26..14
    //   bid 252..255 -> qtile 13, b 4..7
    const int bid = (int)blockIdx.x;
    int qtile, b;
    if (bid < 104)      { qtile = bid >> 3;                b = bid & 7; }
    else if (bid < 108) { qtile = 13;                      b = bid - 104; }
    else if (bid < 148) { qtile = 27 + ((bid - 108) >> 3); b = (bid - 108) & 7; }
    else if (bid < 252) { qtile = 26 - ((bid - 148) >> 3); b = (bid - 148) & 7; }
    else                { qtile = 13;                      b = bid - 252 + 4; }
    const int q0  = qtile * 64;
    const int NKT = 2 * qtile + 2;

    const int tid  = threadIdx.x;
    const int lane = tid & 31;
    const int band = tid >> 5;          // warp = 16-row band
    const int g    = lane >> 2;
    const int tig  = lane & 3;

    // ---- preload: Q (hi+lo) + K0 as group 0; V0 + K1 as group 1 ----
    {
        const __nv_bfloat16* qh = g_Qh + ((size_t)b * NT + q0) * NH;
        const __nv_bfloat16* ql = g_Ql + ((size_t)b * NT + q0) * NH;
        #pragma unroll
        for (int i = 0; i < 16; i++) {
            int c = tid + i * 128;
            int cc = c & 1023;
            int row = cc >> 4, col = cc & 15;
            const __nv_bfloat16* src = (c < 1024 ? qh : ql) + row * NH + col * 8;
            uint32_t dst = sb + (c < 1024 ? 0u : 17408u) + row * 272 + col * 16;
            CPA16(dst, src);
        }
        load_K_tile(sb, b, 0, 0, tid);
    }
    CP_COMMIT;
    load_V_tile(sb, b, 0, 0, tid);
    load_K_tile(sb, b, 1, 1, tid);
    CP_COMMIT;
    CP_WAIT(1);           // group 0 (Q, K0) done
    __syncthreads();

    float m0 = -INFINITY, m1 = -INFINITY, l0 = 0.f, l1 = 0.f;
    float oacc[16][4];
    #pragma unroll
    for (int n = 0; n < 16; n++)
        #pragma unroll
        for (int e = 0; e < 4; e++) oacc[n][e] = 0.f;

    const int r0a = q0 + band * 16 + g;            // row for c0/c1
    const char* qbase = smc + (band * 16 + g) * 272 + tig * 4;

    for (int kt = 0; kt < NKT; kt++) {
        const int st = kt & 1;
        const char* Kbase = smc + 34816 + st * 17408;
        const char* Vbase = smc + 69632 + st * 20480;

        // ---- S = Q K^T : warp tile 16 x 32, k=128 ----
        float cf[4][4];
        #pragma unroll
        for (int nf = 0; nf < 4; nf++)
            #pragma unroll
            for (int e = 0; e < 4; e++) cf[nf][e] = 0.f;

        #pragma unroll
        for (int ks = 0; ks < 8; ks++) {
            const char* qp = qbase + ks * 32;
            uint32_t qhf[4] = { *(const uint32_t*)qp,
                                *(const uint32_t*)(qp + 8*272),
                                *(const uint32_t*)(qp + 16),
                                *(const uint32_t*)(qp + 8*272 + 16) };
            uint32_t qlf[4] = { *(const uint32_t*)(qp + 17408),
                                *(const uint32_t*)(qp + 17408 + 8*272),
                                *(const uint32_t*)(qp + 17408 + 16),
                                *(const uint32_t*)(qp + 17408 + 8*272 + 16) };
            #pragma unroll
            for (int nf = 0; nf < 4; nf++) {
                const char* kp = Kbase + (nf * 8 + g) * 272 + ks * 32 + tig * 4;
                uint32_t bh[2] = { *(const uint32_t*)kp, *(const uint32_t*)(kp + 16) };
                uint32_t bl[2] = { *(const uint32_t*)(kp + 8704),
                                   *(const uint32_t*)(kp + 8704 + 16) };
                mma_bf16(cf[nf], qhf, bh);
                mma_bf16(cf[nf], qhf, bl);
                mma_bf16(cf[nf], qlf, bh);
            }
        }

        // ---- causal mask ----
        const int k0 = kt * 32;
        if (k0 + 31 > r0a) {
            #pragma unroll
            for (int nf = 0; nf < 4; nf++) {
                int cb = k0 + nf * 8 + 2 * tig;
                if (cb     > r0a)     cf[nf][0] = -INFINITY;
                if (cb + 1 > r0a)     cf[nf][1] = -INFINITY;
                if (cb     > r0a + 8) cf[nf][2] = -INFINITY;
                if (cb + 1 > r0a + 8) cf[nf][3] = -INFINITY;
            }
        }

        // ---- online softmax (registers + quad shuffles only) ----
        float rx0 = -INFINITY, rx1 = -INFINITY;
        #pragma unroll
        for (int nf = 0; nf < 4; nf++) {
            rx0 = fmaxf(rx0, fmaxf(cf[nf][0], cf[nf][1]));
            rx1 = fmaxf(rx1, fmaxf(cf[nf][2], cf[nf][3]));
        }
        rx0 = fmaxf(rx0, __shfl_xor_sync(0xffffffffu, rx0, 1));
        rx0 = fmaxf(rx0, __shfl_xor_sync(0xffffffffu, rx0, 2));
        rx1 = fmaxf(rx1, __shfl_xor_sync(0xffffffffu, rx1, 1));
        rx1 = fmaxf(rx1, __shfl_xor_sync(0xffffffffu, rx1, 2));
        float mn0 = fmaxf(m0, rx0), mn1 = fmaxf(m1, rx1);
        float al0 = (m0 == -INFINITY) ? 0.f : __expf(m0 - mn0);
        float al1 = (m1 == -INFINITY) ? 0.f : __expf(m1 - mn1);
        float rs0 = 0.f, rs1 = 0.f;
        #pragma unroll
        for (int nf = 0; nf < 4; nf++) {
            cf[nf][0] = (cf[nf][0] == -INFINITY) ? 0.f : __expf(cf[nf][0] - mn0);
            cf[nf][1] = (cf[nf][1] == -INFINITY) ? 0.f : __expf(cf[nf][1] - mn0);
            cf[nf][2] = (cf[nf][2] == -INFINITY) ? 0.f : __expf(cf[nf][2] - mn1);
            cf[nf][3] = (cf[nf][3] == -INFINITY) ? 0.f : __expf(cf[nf][3] - mn1);
            rs0 += cf[nf][0] + cf[nf][1];
            rs1 += cf[nf][2] + cf[nf][3];
        }
        rs0 += __shfl_xor_sync(0xffffffffu, rs0, 1);
        rs0 += __shfl_xor_sync(0xffffffffu, rs0, 2);
        rs1 += __shfl_xor_sync(0xffffffffu, rs1, 1);
        rs1 += __shfl_xor_sync(0xffffffffu, rs1, 2);
        m0 = mn0; m1 = mn1;
        l0 = l0 * al0 + rs0;
        l1 = l1 * al1 + rs1;

        // rescale O
        #pragma unroll
        for (int n = 0; n < 16; n++) {
            oacc[n][0] *= al0; oacc[n][1] *= al0;
            oacc[n][2] *= al1; oacc[n][3] *= al1;
        }

        // P -> bf16 split A-fragments (c-frag layout == A-frag layout)
        uint32_t pah[2][4], pal[2][4];
        #pragma unroll
        for (int kc = 0; kc < 2; kc++) {
            bsplit2(cf[2*kc][0],   cf[2*kc][1],   pah[kc][0], pal[kc][0]);
            bsplit2(cf[2*kc][2],   cf[2*kc][3],   pah[kc][1], pal[kc][1]);
            bsplit2(cf[2*kc+1][0], cf[2*kc+1][1], pah[kc][2], pal[kc][2]);
            bsplit2(cf[2*kc+1][2], cf[2*kc+1][3], pah[kc][3], pal[kc][3]);
        }

        // ---- rotate buffers: issue K(kt+2) -> K st, V(kt+1) -> V st^1 ----
        __syncthreads();                       // everyone done with K st, V st^1
        if (kt + 2 < NKT) load_K_tile(sb, b, kt + 2, st, tid);
        if (kt + 1 < NKT) load_V_tile(sb, b, kt + 1, st ^ 1, tid);
        CP_COMMIT;
        CP_WAIT(1);                            // V(kt) + K(kt+1) ready
        __syncthreads();

        // ---- O += P V : 16 n-frags (128 d), k=32 ----
        #pragma unroll
        for (int n = 0; n < 16; n++) {
            #pragma unroll
            for (int kc = 0; kc < 2; kc++) {
                const char* vp = Vbase + (n * 8 + g) * 80 + kc * 32 + tig * 4;
                uint32_t bh[2] = { *(const uint32_t*)vp, *(const uint32_t*)(vp + 16) };
                uint32_t bl[2] = { *(const uint32_t*)(vp + 10240),
                                   *(const uint32_t*)(vp + 10240 + 16) };
                mma_bf16(oacc[n], pah[kc], bh);
                mma_bf16(oacc[n], pah[kc], bl);
                mma_bf16(oacc[n], pal[kc], bh);
            }
        }
    }

    // ---- epilogue ----
    const float il0 = 1.f / l0, il1 = 1.f / l1;
    float* Og  = out + ((size_t)b * NT + q0 + band * 16 + g) * NH;
    float* Og8 = Og + 8 * NH;
    #pragma unroll
    for (int n = 0; n < 16; n++) {
        const int cc = n * 8 + 2 * tig;
        *(float2*)&Og[cc]  = make_float2(oacc[n][0] * il0, oacc[n][1] * il0);
        *(float2*)&Og8[cc] = make_float2(oacc[n][2] * il1, oacc[n][3] * il1);
    }
}

// ---------------------------------------------------------------------------
extern "C" void kernel_launch(void* const* d_in, const int* in_sizes, int n_in,
                              void* d_out, int out_size) {
    const float* x  = (const float*)d_in[0];
    const float* Wq = (const float*)d_in[1];
    const float* Wk = (const float*)d_in[2];
    const float* Wv = (const float*)d_in[3];
    float* out = (float*)d_out;

    cudaFuncSetAttribute(qkv_mma_kernel,
                         cudaFuncAttributeMaxDynamicSharedMemorySize, QKV_SMEM);
    qkv_mma_kernel<<<dim3(NBT / 128, 3), 256, QKV_SMEM>>>(x, Wq, Wk, Wv);

    cudaFuncSetAttribute(attn_kernel,
                         cudaFuncAttributeMaxDynamicSharedMemorySize, ATTN_SMEM);
    attn_kernel<<<256, 128, ATTN_SMEM>>>(out);
}

// round 10
// speedup vs baseline: 3.7290x; 1.3981x over previous
#include <cuda_runtime.h>
#include <cuda_bf16.h>
#include <math.h>
#include <stdint.h>

#define NB 8
#define NT 2048
#define NC 1024
#define NH 128
#define NBT (NB*NT)

// bf16 hi/lo split scratch produced by qkv kernel
__device__ __nv_bfloat16 g_Qh[NBT*NH];   // Q * scale, [b][t][d]
__device__ __nv_bfloat16 g_Ql[NBT*NH];
__device__ __nv_bfloat16 g_Kh[NBT*NH];   // [b][t][d]
__device__ __nv_bfloat16 g_Kl[NBT*NH];
__device__ __nv_bfloat16 g_Vth[NB*NH*NT]; // transposed: [b][d][t]
__device__ __nv_bfloat16 g_Vtl[NB*NH*NT];

// ===========================================================================
// MMA helpers (generic sm_80+ PTX)
// ===========================================================================
__device__ __forceinline__ void mma_bf16(float* d, const uint32_t* a, const uint32_t* b) {
    asm volatile(
        "mma.sync.aligned.m16n8k16.row.col.f32.bf16.bf16.f32 "
        "{%0,%1,%2,%3}, {%4,%5,%6,%7}, {%8,%9}, {%0,%1,%2,%3};"
        : "+f"(d[0]), "+f"(d[1]), "+f"(d[2]), "+f"(d[3])
        : "r"(a[0]), "r"(a[1]), "r"(a[2]), "r"(a[3]), "r"(b[0]), "r"(b[1]));
}
__device__ __forceinline__ void bsplit2(float x, float y, uint32_t& h, uint32_t& l) {
    __nv_bfloat162 hh = __floats2bfloat162_rn(x, y);
    float rx = x - __bfloat162float(hh.x);
    float ry = y - __bfloat162float(hh.y);
    __nv_bfloat162 ll = __floats2bfloat162_rn(rx, ry);
    h = *(uint32_t*)&hh;
    l = *(uint32_t*)&ll;
}
__device__ __forceinline__ uint32_t smem_u32(const void* p) {
    uint32_t a;
    asm("{ .reg .u64 t; cvta.to.shared.u64 t, %1; cvt.u32.u64 %0, t; }" : "=r"(a) : "l"(p));
    return a;
}
#define CPA16(dst, src) \
    asm volatile("cp.async.cg.shared.global [%0], [%1], 16;" :: "r"(dst), "l"(src))
#define CP_COMMIT asm volatile("cp.async.commit_group;" ::: "memory")
#define CP_WAIT(n) asm volatile("cp.async.wait_group %0;" :: "n"(n) : "memory")

// ===========================================================================
// QKV projection, bf16 3-term split GEMM (m16n8k16).
// CTA: 128(M) x 128(N), K chunked by 32 (2 MMA k-steps), double-buffered.
// Stages hold PRE-SPLIT bf16 planes Ah/Al/Bh/Bl [128 rows][40 cols pad].
// 8 warps: warpM = wid&3 (32 rows), warpN = wid>>2 (64 cols).
// Epilogue emits bf16 hi/lo: Q (pre-scaled), K row-major; V transposed.
// ===========================================================================
#define KC 32
#define ROWW 20                       // uint32 words per plane row (40 bf16)
#define PLANE (128 * ROWW)            // 2560 u32 per plane
#define STAGEW (4 * PLANE)            // Ah, Al, Bh, Bl
#define QKV_SMEM (2 * STAGEW * 4)     // 81920 bytes

__global__ __launch_bounds__(256, 1)
void qkv_mma_kernel(const float* __restrict__ x,
                    const float* __restrict__ Wq,
                    const float* __restrict__ Wk,
                    const float* __restrict__ Wv) {
    extern __shared__ uint32_t smu[];

    const float* __restrict__ W = (blockIdx.y == 0) ? Wq : (blockIdx.y == 1) ? Wk : Wv;

    const int tid  = threadIdx.x;
    const int wid  = tid >> 5;
    const int lane = tid & 31;
    const int g    = lane >> 2;
    const int tig  = lane & 3;
    const int m0   = blockIdx.x * 128;

    // cooperative load mapping: 4 float4 per thread per tile
    const int r0 = tid >> 3;           // base row (+32 per it)
    const int c4 = (tid & 7) * 4;      // col within 32-chunk
    const int wbase = (c4 >> 1);       // u32 word within row
    const float* xb = x + (size_t)(m0 + r0) * NC + c4;
    const float* wb = W + (size_t)r0 * NC + c4;

    // split a float4 into bf16 hi/lo u32 pairs and store to planes
    auto store_tile = [&](uint32_t* Ph, uint32_t* Pl, int row, float4 v) {
        uint32_t h01, l01, h23, l23;
        bsplit2(v.x, v.y, h01, l01);
        bsplit2(v.z, v.w, h23, l23);
        int wi = row * ROWW + wbase;
        Ph[wi] = h01; Ph[wi + 1] = h23;
        Pl[wi] = l01; Pl[wi + 1] = l23;
    };

    // load chunk 0 into stage 0
    {
        uint32_t* Ah = smu;
        uint32_t* Al = smu + PLANE;
        uint32_t* Bh = smu + 2 * PLANE;
        uint32_t* Bl = smu + 3 * PLANE;
        #pragma unroll
        for (int it = 0; it < 4; it++) {
            store_tile(Ah, Al, r0 + 32*it, *(const float4*)(xb + (size_t)(32*it) * NC));
            store_tile(Bh, Bl, r0 + 32*it, *(const float4*)(wb + (size_t)(32*it) * NC));
        }
    }
    __syncthreads();

    float acc[2][8][4];
    #pragma unroll
    for (int mf = 0; mf < 2; mf++)
        #pragma unroll
        for (int nf = 0; nf < 8; nf++)
            #pragma unroll
            for (int i = 0; i < 4; i++) acc[mf][nf][i] = 0.f;

    const int mrow  = (wid & 3) * 32 + g;
    const int nbase = (wid >> 2) * 64 + g;

    for (int c = 0; c < NC / KC; c++) {
        const int st = c & 1;
        const uint32_t* Ah = smu + st * STAGEW;
        const uint32_t* Al = Ah + PLANE;
        const uint32_t* Bh = Ah + 2 * PLANE;
        const uint32_t* Bl = Ah + 3 * PLANE;

        float4 pa[4], pb[4];
        if (c < NC / KC - 1) {
            const int kn = (c + 1) * KC;
            #pragma unroll
            for (int it = 0; it < 4; it++) {
                pa[it] = *(const float4*)(xb + (size_t)(32*it) * NC + kn);
                pb[it] = *(const float4*)(wb + (size_t)(32*it) * NC + kn);
            }
        }

        #pragma unroll
        for (int ks = 0; ks < 2; ks++) {            // two k16 steps
            const int ko = ks * 8 + tig;            // word offset in row
            uint32_t ahf[2][4], alf[2][4];
            #pragma unroll
            for (int mf = 0; mf < 2; mf++) {
                const int base = (mrow + mf * 16) * ROWW + ko;
                ahf[mf][0] = Ah[base];
                ahf[mf][1] = Ah[base + 8 * ROWW];
                ahf[mf][2] = Ah[base + 4];
                ahf[mf][3] = Ah[base + 8 * ROWW + 4];
                alf[mf][0] = Al[base];
                alf[mf][1] = Al[base + 8 * ROWW];
                alf[mf][2] = Al[base + 4];
                alf[mf][3] = Al[base + 8 * ROWW + 4];
            }
            #pragma unroll
            for (int nf = 0; nf < 8; nf++) {
                const int bb = (nbase + nf * 8) * ROWW + ko;
                uint32_t bh[2] = { Bh[bb], Bh[bb + 4] };
                uint32_t bl[2] = { Bl[bb], Bl[bb + 4] };
                #pragma unroll
                for (int mf = 0; mf < 2; mf++) {
                    mma_bf16(acc[mf][nf], ahf[mf], bh);
                    mma_bf16(acc[mf][nf], ahf[mf], bl);
                    mma_bf16(acc[mf][nf], alf[mf], bh);
                }
            }
        }

        if (c < NC / KC - 1) {
            uint32_t* Ad = smu + (st ^ 1) * STAGEW;
            uint32_t* Ald = Ad + PLANE;
            uint32_t* Bd  = Ad + 2 * PLANE;
            uint32_t* Bld = Ad + 3 * PLANE;
            __syncthreads();
            #pragma unroll
            for (int it = 0; it < 4; it++) {
                store_tile(Ad,  Ald, r0 + 32*it, pa[it]);
                store_tile(Bd,  Bld, r0 + 32*it, pb[it]);
            }
        }
        __syncthreads();
    }

    // ---- epilogue: bf16 hi/lo outputs for the attention kernel ----
    if (blockIdx.y < 2) {
        __nv_bfloat16* oh = (blockIdx.y == 0) ? g_Qh : g_Kh;
        __nv_bfloat16* ol = (blockIdx.y == 0) ? g_Ql : g_Kl;
        const float sc = (blockIdx.y == 0) ? 0.08838834764831845f : 1.0f;
        #pragma unroll
        for (int mf = 0; mf < 2; mf++) {
            const int crow = m0 + mrow + mf * 16;
            #pragma unroll
            for (int nf = 0; nf < 8; nf++) {
                const int ccol = (wid >> 2) * 64 + nf * 8 + tig * 2;
                uint32_t h01, l01, h23, l23;
                bsplit2(acc[mf][nf][0]*sc, acc[mf][nf][1]*sc, h01, l01);
                bsplit2(acc[mf][nf][2]*sc, acc[mf][nf][3]*sc, h23, l23);
                *(uint32_t*)&oh[(size_t)crow * NH + ccol]       = h01;
                *(uint32_t*)&ol[(size_t)crow * NH + ccol]       = l01;
                *(uint32_t*)&oh[(size_t)(crow + 8) * NH + ccol] = h23;
                *(uint32_t*)&ol[(size_t)(crow + 8) * NH + ccol] = l23;
            }
        }
    } else {
        // V: transpose to [d][t] via smem, then coalesced writes
        __nv_bfloat16* svh = (__nv_bfloat16*)smu;      // [128 d][136]
        __nv_bfloat16* svl = svh + 128 * 136;
        __syncthreads();
        #pragma unroll
        for (int mf = 0; mf < 2; mf++) {
            const int rl = mrow + mf * 16;   // local 0..127
            #pragma unroll
            for (int nf = 0; nf < 8; nf++) {
                const int ccol = (wid >> 2) * 64 + nf * 8 + tig * 2;
                #pragma unroll
                for (int e = 0; e < 4; e++) {
                    float a = acc[mf][nf][e];
                    int d = ccol + (e & 1);
                    int m = rl + (e >> 1) * 8;
                    __nv_bfloat16 h = __float2bfloat16(a);
                    __nv_bfloat16 l = __float2bfloat16(a - __bfloat162float(h));
                    svh[d * 136 + m] = h;
                    svl[d * 136 + m] = l;
                }
            }
        }
        __syncthreads();
        const int b  = m0 >> 11;
        const int t0 = m0 & 2047;
        #pragma unroll
        for (int i = 0; i < 16; i++) {
            int c = tid + i * 256;          // 4096 chunks of 16B
            int cc = c & 2047;
            int d = cc >> 4, col = cc & 15;
            const __nv_bfloat16* src = (c < 2048 ? svh : svl) + d * 136 + col * 8;
            __nv_bfloat16* dst = (c < 2048 ? g_Vth : g_Vtl)
                                 + ((size_t)b * NH + d) * NT + t0 + col * 8;
            *(float4*)dst = *(const float4*)src;
        }
    }
}

// ===========================================================================
// Flash attention with mma.sync bf16 split (unchanged from round 9; 144us).
// ===========================================================================
#define ATTN_SMEM 110592

__device__ __forceinline__ void load_K_tile(uint32_t sb, int b, int kt, int st, int tid) {
    const __nv_bfloat16* kh = g_Kh + ((size_t)b * NT + kt * 32) * NH;
    const __nv_bfloat16* kl = g_Kl + ((size_t)b * NT + kt * 32) * NH;
    uint32_t base = sb + 34816u + (uint32_t)st * 17408u;
    #pragma unroll
    for (int i = 0; i < 8; i++) {
        int c = tid + i * 128;
        int cc = c & 511;
        int row = cc >> 4, col = cc & 15;
        const __nv_bfloat16* src = (c < 512 ? kh : kl) + row * NH + col * 8;
        uint32_t dst = base + (c < 512 ? 0u : 8704u) + row * 272 + col * 16;
        CPA16(dst, src);
    }
}
__device__ __forceinline__ void load_V_tile(uint32_t sb, int b, int kt, int st, int tid) {
    const __nv_bfloat16* vh = g_Vth + (size_t)b * NH * NT + kt * 32;
    const __nv_bfloat16* vl = g_Vtl + (size_t)b * NH * NT + kt * 32;
    uint32_t base = sb + 69632u + (uint32_t)st * 20480u;
    #pragma unroll
    for (int i = 0; i < 8; i++) {
        int c = tid + i * 128;
        int cc = c & 511;
        int row = cc >> 2, col = cc & 3;
        const __nv_bfloat16* src = (c < 512 ? vh : vl) + (size_t)row * NT + col * 8;
        uint32_t dst = base + (c < 512 ? 0u : 10240u) + row * 80 + col * 16;
        CPA16(dst, src);
    }
}

__global__ __launch_bounds__(128, 2)
void attn_kernel(float* __restrict__ out) {
    extern __shared__ char smc[];
    const uint32_t sb = smem_u32(smc);

    // Exact-cover balanced mapping (each (qtile,b) once)
    const int bid = (int)blockIdx.x;
    int qtile, b;
    if (bid < 104)      { qtile = bid >> 3;                b = bid & 7; }
    else if (bid < 108) { qtile = 13;                      b = bid - 104; }
    else if (bid < 148) { qtile = 27 + ((bid - 108) >> 3); b = (bid - 108) & 7; }
    else if (bid < 252) { qtile = 26 - ((bid - 148) >> 3); b = (bid - 148) & 7; }
    else                { qtile = 13;                      b = bid - 252 + 4; }
    const int q0  = qtile * 64;
    const int NKT = 2 * qtile + 2;

    const int tid  = threadIdx.x;
    const int lane = tid & 31;
    const int band = tid >> 5;
    const int g    = lane >> 2;
    const int tig  = lane & 3;

    {
        const __nv_bfloat16* qh = g_Qh + ((size_t)b * NT + q0) * NH;
        const __nv_bfloat16* ql = g_Ql + ((size_t)b * NT + q0) * NH;
        #pragma unroll
        for (int i = 0; i < 16; i++) {
            int c = tid + i * 128;
            int cc = c & 1023;
            int row = cc >> 4, col = cc & 15;
            const __nv_bfloat16* src = (c < 1024 ? qh : ql) + row * NH + col * 8;
            uint32_t dst = sb + (c < 1024 ? 0u : 17408u) + row * 272 + col * 16;
            CPA16(dst, src);
        }
        load_K_tile(sb, b, 0, 0, tid);
    }
    CP_COMMIT;
    load_V_tile(sb, b, 0, 0, tid);
    load_K_tile(sb, b, 1, 1, tid);
    CP_COMMIT;
    CP_WAIT(1);
    __syncthreads();

    float m0 = -INFINITY, m1 = -INFINITY, l0 = 0.f, l1 = 0.f;
    float oacc[16][4];
    #pragma unroll
    for (int n = 0; n < 16; n++)
        #pragma unroll
        for (int e = 0; e < 4; e++) oacc[n][e] = 0.f;

    const int r0a = q0 + band * 16 + g;
    const char* qbase = smc + (band * 16 + g) * 272 + tig * 4;

    for (int kt = 0; kt < NKT; kt++) {
        const int st = kt & 1;
        const char* Kbase = smc + 34816 + st * 17408;
        const char* Vbase = smc + 69632 + st * 20480;

        float cf[4][4];
        #pragma unroll
        for (int nf = 0; nf < 4; nf++)
            #pragma unroll
            for (int e = 0; e < 4; e++) cf[nf][e] = 0.f;

        #pragma unroll
        for (int ks = 0; ks < 8; ks++) {
            const char* qp = qbase + ks * 32;
            uint32_t qhf[4] = { *(const uint32_t*)qp,
                                *(const uint32_t*)(qp + 8*272),
                                *(const uint32_t*)(qp + 16),
                                *(const uint32_t*)(qp + 8*272 + 16) };
            uint32_t qlf[4] = { *(const uint32_t*)(qp + 17408),
                                *(const uint32_t*)(qp + 17408 + 8*272),
                                *(const uint32_t*)(qp + 17408 + 16),
                                *(const uint32_t*)(qp + 17408 + 8*272 + 16) };
            #pragma unroll
            for (int nf = 0; nf < 4; nf++) {
                const char* kp = Kbase + (nf * 8 + g) * 272 + ks * 32 + tig * 4;
                uint32_t bh[2] = { *(const uint32_t*)kp, *(const uint32_t*)(kp + 16) };
                uint32_t bl[2] = { *(const uint32_t*)(kp + 8704),
                                   *(const uint32_t*)(kp + 8704 + 16) };
                mma_bf16(cf[nf], qhf, bh);
                mma_bf16(cf[nf], qhf, bl);
                mma_bf16(cf[nf], qlf, bh);
            }
        }

        const int k0 = kt * 32;
        if (k0 + 31 > r0a) {
            #pragma unroll
            for (int nf = 0; nf < 4; nf++) {
                int cb = k0 + nf * 8 + 2 * tig;
                if (cb     > r0a)     cf[nf][0] = -INFINITY;
                if (cb + 1 > r0a)     cf[nf][1] = -INFINITY;
                if (cb     > r0a + 8) cf[nf][2] = -INFINITY;
                if (cb + 1 > r0a + 8) cf[nf][3] = -INFINITY;
            }
        }

        float rx0 = -INFINITY, rx1 = -INFINITY;
        #pragma unroll
        for (int nf = 0; nf < 4; nf++) {
            rx0 = fmaxf(rx0, fmaxf(cf[nf][0], cf[nf][1]));
            rx1 = fmaxf(rx1, fmaxf(cf[nf][2], cf[nf][3]));
        }
        rx0 = fmaxf(rx0, __shfl_xor_sync(0xffffffffu, rx0, 1));
        rx0 = fmaxf(rx0, __shfl_xor_sync(0xffffffffu, rx0, 2));
        rx1 = fmaxf(rx1, __shfl_xor_sync(0xffffffffu, rx1, 1));
        rx1 = fmaxf(rx1, __shfl_xor_sync(0xffffffffu, rx1, 2));
        float mn0 = fmaxf(m0, rx0), mn1 = fmaxf(m1, rx1);
        float al0 = (m0 == -INFINITY) ? 0.f : __expf(m0 - mn0);
        float al1 = (m1 == -INFINITY) ? 0.f : __expf(m1 - mn1);
        float rs0 = 0.f, rs1 = 0.f;
        #pragma unroll
        for (int nf = 0; nf < 4; nf++) {
            cf[nf][0] = (cf[nf][0] == -INFINITY) ? 0.f : __expf(cf[nf][0] - mn0);
            cf[nf][1] = (cf[nf][1] == -INFINITY) ? 0.f : __expf(cf[nf][1] - mn0);
            cf[nf][2] = (cf[nf][2] == -INFINITY) ? 0.f : __expf(cf[nf][2] - mn1);
            cf[nf][3] = (cf[nf][3] == -INFINITY) ? 0.f : __expf(cf[nf][3] - mn1);
            rs0 += cf[nf][0] + cf[nf][1];
            rs1 += cf[nf][2] + cf[nf][3];
        }
        rs0 += __shfl_xor_sync(0xffffffffu, rs0, 1);
        rs0 += __shfl_xor_sync(0xffffffffu, rs0, 2);
        rs1 += __shfl_xor_sync(0xffffffffu, rs1, 1);
        rs1 += __shfl_xor_sync(0xffffffffu, rs1, 2);
        m0 = mn0; m1 = mn1;
        l0 = l0 * al0 + rs0;
        l1 = l1 * al1 + rs1;

        #pragma unroll
        for (int n = 0; n < 16; n++) {
            oacc[n][0] *= al0; oacc[n][1] *= al0;
            oacc[n][2] *= al1; oacc[n][3] *= al1;
        }

        uint32_t pah[2][4], pal[2][4];
        #pragma unroll
        for (int kc = 0; kc < 2; kc++) {
            bsplit2(cf[2*kc][0],   cf[2*kc][1],   pah[kc][0], pal[kc][0]);
            bsplit2(cf[2*kc][2],   cf[2*kc][3],   pah[kc][1], pal[kc][1]);
            bsplit2(cf[2*kc+1][0], cf[2*kc+1][1], pah[kc][2], pal[kc][2]);
            bsplit2(cf[2*kc+1][2], cf[2*kc+1][3], pah[kc][3], pal[kc][3]);
        }

        __syncthreads();
        if (kt + 2 < NKT) load_K_tile(sb, b, kt + 2, st, tid);
        if (kt + 1 < NKT) load_V_tile(sb, b, kt + 1, st ^ 1, tid);
        CP_COMMIT;
        CP_WAIT(1);
        __syncthreads();

        #pragma unroll
        for (int n = 0; n < 16; n++) {
            #pragma unroll
            for (int kc = 0; kc < 2; kc++) {
                const char* vp = Vbase + (n * 8 + g) * 80 + kc * 32 + tig * 4;
                uint32_t bh[2] = { *(const uint32_t*)vp, *(const uint32_t*)(vp + 16) };
                uint32_t bl[2] = { *(const uint32_t*)(vp + 10240),
                                   *(const uint32_t*)(vp + 10240 + 16) };
                mma_bf16(oacc[n], pah[kc], bh);
                mma_bf16(oacc[n], pah[kc], bl);
                mma_bf16(oacc[n], pal[kc], bh);
            }
        }
    }

    const float il0 = 1.f / l0, il1 = 1.f / l1;
    float* Og  = out + ((size_t)b * NT + q0 + band * 16 + g) * NH;
    float* Og8 = Og + 8 * NH;
    #pragma unroll
    for (int n = 0; n < 16; n++) {
        const int cc = n * 8 + 2 * tig;
        *(float2*)&Og[cc]  = make_float2(oacc[n][0] * il0, oacc[n][1] * il0);
        *(float2*)&Og8[cc] = make_float2(oacc[n][2] * il1, oacc[n][3] * il1);
    }
}

// ---------------------------------------------------------------------------
extern "C" void kernel_launch(void* const* d_in, const int* in_sizes, int n_in,
                              void* d_out, int out_size) {
    const float* x  = (const float*)d_in[0];
    const float* Wq = (const float*)d_in[1];
    const float* Wk = (const float*)d_in[2];
    const float* Wv = (const float*)d_in[3];
    float* out = (float*)d_out;

    cudaFuncSetAttribute(qkv_mma_kernel,
                         cudaFuncAttributeMaxDynamicSharedMemorySize, QKV_SMEM);
    qkv_mma_kernel<<<dim3(NBT / 128, 3), 256, QKV_SMEM>>>(x, Wq, Wk, Wv);

    cudaFuncSetAttribute(attn_kernel,
                         cudaFuncAttributeMaxDynamicSharedMemorySize, ATTN_SMEM);
    attn_kernel<<<256, 128, ATTN_SMEM>>>(out);
}